// round 14
// baseline (speedup 1.0000x reference)
#include <cuda_runtime.h>
#include <math.h>

#define Bq 64
#define Sq 256
#define Hq 512
#define G4 2048
#define Wq 512
#define NBLK 128u

// ---------------- scratch ----------------
__device__ float d_WihT_enc[Sq * G4];
__device__ float d_WihT_dec[Sq * G4];
__device__ float d_WhhT_enc[Hq * G4];
__device__ float d_WhhT_dec[Hq * G4];
__device__ float d_w1T[Hq * Wq];
__device__ float d_w2T[Hq * Wq];
__device__ float d_bias_enc[G4];
__device__ float d_bias_dec[G4];
__device__ float d_Xenc[(size_t)Bq * Sq * G4];
__device__ float d_Xdec[(size_t)Bq * Sq * G4];
__device__ float d_h[Bq * Hq];
__device__ float d_c[Bq * Hq];
__device__ float d_enc_out[(size_t)Bq * Sq * Hq]; // [B,S,H]
__device__ float d_e1[(size_t)Bq * Sq * Wq];      // [B,S,W]
__device__ float d_gpart[16 * (size_t)Bq * G4];
__device__ float d_hw2part[8 * Bq * Wq];
__device__ float d_sc[Bq * Sq];

// ---------------- monotonic-counter grid barrier ----------------
__device__ __align__(128) unsigned g_ctr_enc[32];
__device__ __align__(128) unsigned g_ctr_dec[32];

__device__ __forceinline__ void gbar_ctr(unsigned* ctr, unsigned target) {
    __syncthreads();
    if (threadIdx.x == 0) {
        unsigned old, one = 1u;
        asm volatile("atom.release.gpu.add.u32 %0, [%1], %2;"
                     : "=r"(old) : "l"(ctr), "r"(one) : "memory");
        unsigned v;
        do {
            asm volatile("ld.acquire.gpu.u32 %0, [%1];" : "=r"(v) : "l"(ctr) : "memory");
        } while (v < target);
    }
    __syncthreads();
}

#define NBAR_SYNC(id, cnt) asm volatile("bar.sync %0, %1;" ::"r"(id), "r"(cnt) : "memory")

// ---------------- packed fp32x2 helpers ----------------
__device__ __forceinline__ unsigned long long pack2(float x) {
    unsigned long long r;
    unsigned u = __float_as_uint(x);
    asm("mov.b64 %0, {%1, %1};" : "=l"(r) : "r"(u));
    return r;
}
__device__ __forceinline__ void fma2(unsigned long long& d, unsigned long long a,
                                     unsigned long long b) {
    asm("fma.rn.f32x2 %0, %1, %2, %0;" : "+l"(d) : "l"(a), "l"(b));
}
__device__ __forceinline__ float2 unpk(unsigned long long v) {
    float2 f;
    asm("mov.b64 {%0, %1}, %2;" : "=f"(f.x), "=f"(f.y) : "l"(v));
    return f;
}

// ---------------- math ----------------
__device__ __forceinline__ float ftanh_acc(float x) {
    float ax = fabsf(x);
    float e = __expf(-2.f * ax);
    float r = __fdividef(1.f - e, 1.f + e);
    return copysignf(r, x);
}
__device__ __forceinline__ float fsigmoid(float x) {
    return __fdividef(1.f, 1.f + __expf(-x));
}
__device__ __forceinline__ float htanh(float x) {
    float y;
    asm("tanh.approx.f32 %0, %1;" : "=f"(y) : "f"(x));
    return y;
}

// ---------------- setup: all 6 transposes in ONE kernel ----------------
__global__ void transpose_all_k(const float* __restrict__ eWih, const float* __restrict__ dWih,
                                const float* __restrict__ eWhh, const float* __restrict__ dWhh,
                                const float* __restrict__ w1, const float* __restrict__ w2) {
    __shared__ float tile[32][33];
    int tb = blockIdx.x;
    const float* A;
    float* At;
    int R, C, lt;
    if (tb < 512)       { A = eWih; At = d_WihT_enc; R = G4; C = Sq; lt = tb; }
    else if (tb < 1024) { A = dWih; At = d_WihT_dec; R = G4; C = Sq; lt = tb - 512; }
    else if (tb < 2048) { A = eWhh; At = d_WhhT_enc; R = G4; C = Hq; lt = tb - 1024; }
    else if (tb < 3072) { A = dWhh; At = d_WhhT_dec; R = G4; C = Hq; lt = tb - 2048; }
    else if (tb < 3328) { A = w1;   At = d_w1T;      R = Wq; C = Hq; lt = tb - 3072; }
    else                { A = w2;   At = d_w2T;      R = Wq; C = Hq; lt = tb - 3328; }
    int ntx = C >> 5;
    int c0 = (lt % ntx) << 5, r0 = (lt / ntx) << 5;
    int tx = threadIdx.x, ty = threadIdx.y;
#pragma unroll
    for (int i = 0; i < 32; i += 8)
        tile[ty + i][tx] = A[(size_t)(r0 + ty + i) * C + c0 + tx];
    __syncthreads();
#pragma unroll
    for (int i = 0; i < 32; i += 8)
        At[(size_t)(c0 + ty + i) * R + r0 + tx] = tile[tx][ty + i];
}

__global__ void prep_small_k(const float* __restrict__ ebih, const float* __restrict__ ebhh,
                             const float* __restrict__ dbih, const float* __restrict__ dbhh) {
    int i = blockIdx.x * 256 + threadIdx.x;
    if (i < G4) {
        d_bias_enc[i] = ebih[i] + ebhh[i];
        d_bias_dec[i] = dbih[i] + dbhh[i];
    }
    if (i < Bq * Hq) {
        d_h[i] = 0.f;
        d_c[i] = 0.f;
    }
    if (i < 32) {
        g_ctr_enc[i] = 0u;
        g_ctr_dec[i] = 0u;
    }
}

// ---------------- big GEMM (f32x2): BM=BN=128, BK=16 ----------------
__global__ __launch_bounds__(256) void gemm128_k(const float* __restrict__ A,
                                                 const float* __restrict__ Bm,
                                                 const float* __restrict__ bias,
                                                 float* __restrict__ C, int N, int K) {
    __shared__ float sA[16][136];
    __shared__ float sB[16][136];
    const int bm = blockIdx.y * 128, bn = blockIdx.x * 128;
    const int tid = threadIdx.x;
    const int tx = tid & 15, ty = tid >> 4;
    unsigned long long acc[8][4] = {};
    for (int k0 = 0; k0 < K; k0 += 16) {
#pragma unroll
        for (int q = 0; q < 2; q++) {
            int f = tid * 2 + q;
            int r = f >> 2, c4 = (f & 3) * 4;
            float4 v = *reinterpret_cast<const float4*>(A + (size_t)(bm + r) * K + k0 + c4);
            sA[c4 + 0][r] = v.x;
            sA[c4 + 1][r] = v.y;
            sA[c4 + 2][r] = v.z;
            sA[c4 + 3][r] = v.w;
        }
#pragma unroll
        for (int q = 0; q < 2; q++) {
            int f = tid * 2 + q;
            int r = f >> 5, c = (f & 31) * 4;
            *reinterpret_cast<float4*>(&sB[r][c]) =
                *reinterpret_cast<const float4*>(Bm + (size_t)(k0 + r) * N + bn + c);
        }
        __syncthreads();
#pragma unroll
        for (int kk = 0; kk < 16; kk++) {
            float4 a0 = *reinterpret_cast<float4*>(&sA[kk][ty * 8]);
            float4 a1 = *reinterpret_cast<float4*>(&sA[kk][ty * 8 + 4]);
            ulonglong2 b0 = *reinterpret_cast<ulonglong2*>(&sB[kk][tx * 8]);
            ulonglong2 b1 = *reinterpret_cast<ulonglong2*>(&sB[kk][tx * 8 + 4]);
            unsigned long long bb[4] = {b0.x, b0.y, b1.x, b1.y};
            unsigned long long aa[8] = {pack2(a0.x), pack2(a0.y), pack2(a0.z), pack2(a0.w),
                                        pack2(a1.x), pack2(a1.y), pack2(a1.z), pack2(a1.w)};
#pragma unroll
            for (int i = 0; i < 8; i++)
#pragma unroll
                for (int j = 0; j < 4; j++) fma2(acc[i][j], aa[i], bb[j]);
        }
        __syncthreads();
    }
#pragma unroll
    for (int i = 0; i < 8; i++) {
        int m = bm + ty * 8 + i;
#pragma unroll
        for (int j = 0; j < 4; j++) {
            int n = bn + tx * 8 + j * 2;
            float2 p = unpk(acc[i][j]);
            if (bias) {
                p.x += bias[n];
                p.y += bias[n + 1];
            }
            *reinterpret_cast<float2*>(&C[(size_t)m * N + n]) = p;
        }
    }
}

// ---------------- device e1 tile (f32x2): 128x128, K=512; A via ldcg ----------------
__device__ void gemm128_tile_f2(const float* __restrict__ A, const float* __restrict__ Bm,
                                float* __restrict__ C, int N, int K, int bm, int bn,
                                float* sAf, float* sBf) {
    const int tid = threadIdx.x;
    const int tx = tid & 15, ty = tid >> 4;
    unsigned long long acc[8][4] = {};
    for (int k0 = 0; k0 < K; k0 += 16) {
#pragma unroll
        for (int q = 0; q < 2; q++) {
            int f = tid * 2 + q;
            int r = f >> 2, c4 = (f & 3) * 4;
            float4 v = __ldcg(reinterpret_cast<const float4*>(A + (size_t)(bm + r) * K + k0 + c4));
            sAf[(c4 + 0) * 136 + r] = v.x;
            sAf[(c4 + 1) * 136 + r] = v.y;
            sAf[(c4 + 2) * 136 + r] = v.z;
            sAf[(c4 + 3) * 136 + r] = v.w;
        }
#pragma unroll
        for (int q = 0; q < 2; q++) {
            int f = tid * 2 + q;
            int r = f >> 5, c = (f & 31) * 4;
            *reinterpret_cast<float4*>(&sBf[r * 136 + c]) =
                *reinterpret_cast<const float4*>(Bm + (size_t)(k0 + r) * N + bn + c);
        }
        __syncthreads();
#pragma unroll
        for (int kk = 0; kk < 16; kk++) {
            float4 a0 = *reinterpret_cast<float4*>(&sAf[kk * 136 + ty * 8]);
            float4 a1 = *reinterpret_cast<float4*>(&sAf[kk * 136 + ty * 8 + 4]);
            ulonglong2 b0 = *reinterpret_cast<ulonglong2*>(&sBf[kk * 136 + tx * 8]);
            ulonglong2 b1 = *reinterpret_cast<ulonglong2*>(&sBf[kk * 136 + tx * 8 + 4]);
            unsigned long long bb[4] = {b0.x, b0.y, b1.x, b1.y};
            unsigned long long aa[8] = {pack2(a0.x), pack2(a0.y), pack2(a0.z), pack2(a0.w),
                                        pack2(a1.x), pack2(a1.y), pack2(a1.z), pack2(a1.w)};
#pragma unroll
            for (int i = 0; i < 8; i++)
#pragma unroll
                for (int j = 0; j < 4; j++) fma2(acc[i][j], aa[i], bb[j]);
        }
        __syncthreads();
    }
#pragma unroll
    for (int i = 0; i < 8; i++) {
        int m = bm + ty * 8 + i;
#pragma unroll
        for (int j = 0; j < 4; j++) {
            float2 p = unpk(acc[i][j]);
            *reinterpret_cast<float2*>(&C[(size_t)m * N + bn + tx * 8 + j * 2]) = p;
        }
    }
}

// ---------------- encoder G unit (f32x2, 256 thr): out 64m x 256n, K=32 ----------------
__device__ __forceinline__ void gemm_G3_unit(const float* __restrict__ Bm, int n0, int k0,
                                             int part, float* sA, float* sB) {
    const int tid = threadIdx.x;
#pragma unroll
    for (int i = 0; i < 2; i++) {
        int f = tid + i * 256;
        int m = f >> 3, kq = (f & 7) * 4;
        float4 av = __ldcg(reinterpret_cast<const float4*>(d_h + m * Hq + k0 + kq));
        sA[(kq + 0) * 68 + m] = av.x;
        sA[(kq + 1) * 68 + m] = av.y;
        sA[(kq + 2) * 68 + m] = av.z;
        sA[(kq + 3) * 68 + m] = av.w;
    }
    const int tr = tid >> 5, tc = tid & 31;
    unsigned long long acc[8][4] = {};
    for (int ch = 0; ch < 2; ch++) {
#pragma unroll
        for (int i = 0; i < 4; i++) {
            int f = tid + i * 256;
            int kk = f >> 6, c = (f & 63) * 4;
            *reinterpret_cast<float4*>(&sB[kk * 256 + c]) =
                *reinterpret_cast<const float4*>(Bm + (size_t)(k0 + ch * 16 + kk) * G4 + n0 + c);
        }
        __syncthreads();
#pragma unroll
        for (int kk = 0; kk < 16; kk++) {
            int kg = ch * 16 + kk;
            float4 a0 = *reinterpret_cast<float4*>(&sA[kg * 68 + tr * 8]);
            float4 a1 = *reinterpret_cast<float4*>(&sA[kg * 68 + tr * 8 + 4]);
            ulonglong2 b0 = *reinterpret_cast<ulonglong2*>(&sB[kk * 256 + tc * 4]);
            ulonglong2 b1 = *reinterpret_cast<ulonglong2*>(&sB[kk * 256 + 128 + tc * 4]);
            unsigned long long aa[8] = {pack2(a0.x), pack2(a0.y), pack2(a0.z), pack2(a0.w),
                                        pack2(a1.x), pack2(a1.y), pack2(a1.z), pack2(a1.w)};
#pragma unroll
            for (int i = 0; i < 8; i++) {
                fma2(acc[i][0], aa[i], b0.x);
                fma2(acc[i][1], aa[i], b0.y);
                fma2(acc[i][2], aa[i], b1.x);
                fma2(acc[i][3], aa[i], b1.y);
            }
        }
        __syncthreads();
    }
#pragma unroll
    for (int i = 0; i < 8; i++) {
        int m = tr * 8 + i;
        float* dst = &d_gpart[(size_t)(part * Bq + m) * G4 + n0 + tc * 4];
        ulonglong2 s0;
        s0.x = acc[i][0];
        s0.y = acc[i][1];
        *reinterpret_cast<ulonglong2*>(dst) = s0;
        ulonglong2 s1;
        s1.x = acc[i][2];
        s1.y = acc[i][3];
        *reinterpret_cast<ulonglong2*>(dst + 128) = s1;
    }
}

// ---------------- decoder G unit (f32x2, 4 WARPS, threads 0..127) ----------------
// unit u (0..127): n0=(u>>3)*128, k0=(u&7)*64, part=u&7
// sA: k-major [64][68]; sB: 16-k chunk [16][132]. Named barrier 1 (128 threads).
__device__ __forceinline__ void gemm_G4w_unit(const float* __restrict__ Bm, int u,
                                              float* sA, float* sB) {
    const int n0 = (u >> 3) * 128, k0 = (u & 7) * 64, part = u & 7;
    const int tid = threadIdx.x;   // 0..127
#pragma unroll
    for (int i = 0; i < 8; i++) {
        int f = tid + i * 128;                // 0..1023
        int m = f >> 4, kq = (f & 15) * 4;
        float4 av = __ldcg(reinterpret_cast<const float4*>(d_h + m * Hq + k0 + kq));
        sA[(kq + 0) * 68 + m] = av.x;
        sA[(kq + 1) * 68 + m] = av.y;
        sA[(kq + 2) * 68 + m] = av.z;
        sA[(kq + 3) * 68 + m] = av.w;
    }
    const int tr = tid >> 4, tc = tid & 15;   // 8 m-groups x 8m, 16 n-groups x 8n
    unsigned long long acc[8][4] = {};
    for (int ch = 0; ch < 4; ch++) {
#pragma unroll
        for (int i = 0; i < 4; i++) {
            int f = tid + i * 128;            // 0..511
            int kk = f >> 5, c = (f & 31) * 4;
            *reinterpret_cast<float4*>(&sB[kk * 132 + c]) =
                *reinterpret_cast<const float4*>(Bm + (size_t)(k0 + ch * 16 + kk) * G4 + n0 + c);
        }
        NBAR_SYNC(1, 128);
#pragma unroll
        for (int kk = 0; kk < 16; kk++) {
            int kg = ch * 16 + kk;
            float4 a0 = *reinterpret_cast<float4*>(&sA[kg * 68 + tr * 8]);
            float4 a1 = *reinterpret_cast<float4*>(&sA[kg * 68 + tr * 8 + 4]);
            ulonglong2 b0 = *reinterpret_cast<ulonglong2*>(&sB[kk * 132 + tc * 4]);
            ulonglong2 b1 = *reinterpret_cast<ulonglong2*>(&sB[kk * 132 + 64 + tc * 4]);
            unsigned long long aa[8] = {pack2(a0.x), pack2(a0.y), pack2(a0.z), pack2(a0.w),
                                        pack2(a1.x), pack2(a1.y), pack2(a1.z), pack2(a1.w)};
#pragma unroll
            for (int i = 0; i < 8; i++) {
                fma2(acc[i][0], aa[i], b0.x);
                fma2(acc[i][1], aa[i], b0.y);
                fma2(acc[i][2], aa[i], b1.x);
                fma2(acc[i][3], aa[i], b1.y);
            }
        }
        NBAR_SYNC(1, 128);
    }
#pragma unroll
    for (int i = 0; i < 8; i++) {
        int m = tr * 8 + i;
        float* dst = &d_gpart[(size_t)(part * Bq + m) * G4 + n0 + tc * 4];
        ulonglong2 s0;
        s0.x = acc[i][0];
        s0.y = acc[i][1];
        *reinterpret_cast<ulonglong2*>(dst) = s0;
        ulonglong2 s1;
        s1.x = acc[i][2];
        s1.y = acc[i][3];
        *reinterpret_cast<ulonglong2*>(dst + 64) = s1;
    }
}

// ---------------- attention for (b, half) by 4 WARPS (threads 128..255) ----------
__device__ __forceinline__ void att_4w(int b, int half, const float4* vt4, float* hw2_s) {
    const int tid2 = threadIdx.x - 128;       // 0..127
    const int lane = tid2 & 31, wid = tid2 >> 5;
#pragma unroll
    for (int r = 0; r < 4; r++) {
        int w = tid2 + r * 128;
        float s = 0.f;
#pragma unroll
        for (int p = 0; p < 8; p++)
            s += __ldcg(&d_hw2part[(size_t)(p * Bq + b) * Wq + w]);
        hw2_s[w] = s;
    }
    NBAR_SYNC(2, 128);
    float4 hv[4];
#pragma unroll
    for (int c = 0; c < 4; c++)
        hv[c] = *reinterpret_cast<float4*>(&hw2_s[(c * 32 + lane) * 4]);

    const int s0 = half * 128;
    float4 ev[4];
    {
        const float* ep = d_e1 + ((size_t)b * Sq + s0 + wid) * Wq;
#pragma unroll
        for (int c = 0; c < 4; c++)
            ev[c] = __ldg(reinterpret_cast<const float4*>(ep + (c * 32 + lane) * 4));
    }
    for (int s = s0 + wid; s < s0 + 128; s += 4) {
        float4 evn[4];
        if (s + 4 < s0 + 128) {
            const float* epn = d_e1 + ((size_t)b * Sq + s + 4) * Wq;
#pragma unroll
            for (int c = 0; c < 4; c++)
                evn[c] = __ldg(reinterpret_cast<const float4*>(epn + (c * 32 + lane) * 4));
        }
        float sum = 0.f;
#pragma unroll
        for (int c = 0; c < 4; c++) {
            sum += vt4[c].x * htanh(ev[c].x + hv[c].x);
            sum += vt4[c].y * htanh(ev[c].y + hv[c].y);
            sum += vt4[c].z * htanh(ev[c].z + hv[c].z);
            sum += vt4[c].w * htanh(ev[c].w + hv[c].w);
        }
#pragma unroll
        for (int off = 16; off; off >>= 1) sum += __shfl_xor_sync(0xffffffffu, sum, off);
        if (lane == 0) d_sc[b * Sq + s] = sum;
#pragma unroll
        for (int c = 0; c < 4; c++) ev[c] = evn[c];
    }
}

// ---------------- W unit (f32x2, 256 thr): out 64m x 32n, K=64 slice ----------------
__device__ __forceinline__ void gemm_W3_unit(const float* __restrict__ w2T, int u,
                                             float* sA, float* sB) {
    const int n0 = (u >> 3) * 32, k0 = (u & 7) * 64, part = u & 7;
    const int tid = threadIdx.x;
#pragma unroll
    for (int i = 0; i < 4; i++) {
        int f = tid + i * 256;
        int m = f >> 4, kq = (f & 15) * 4;
        float4 av = __ldcg(reinterpret_cast<const float4*>(d_h + m * Hq + k0 + kq));
        sA[(kq + 0) * 68 + m] = av.x;
        sA[(kq + 1) * 68 + m] = av.y;
        sA[(kq + 2) * 68 + m] = av.z;
        sA[(kq + 3) * 68 + m] = av.w;
    }
#pragma unroll
    for (int q = 0; q < 2; q++) {
        int f = tid * 2 + q;
        int kk = f >> 3, c = (f & 7) * 4;
        *reinterpret_cast<float4*>(&sB[kk * 36 + c]) =
            *reinterpret_cast<const float4*>(w2T + (size_t)(k0 + kk) * Wq + n0 + c);
    }
    __syncthreads();
    const int tr = tid >> 5, tc = tid & 31;
    unsigned long long acc[4] = {};
#pragma unroll
    for (int kk = 0; kk < 64; kk++) {
        ulonglong2 a01 = *reinterpret_cast<ulonglong2*>(&sA[kk * 68 + tr * 8]);
        ulonglong2 a23 = *reinterpret_cast<ulonglong2*>(&sA[kk * 68 + tr * 8 + 4]);
        unsigned long long bb = pack2(sB[kk * 36 + tc]);
        fma2(acc[0], a01.x, bb);
        fma2(acc[1], a01.y, bb);
        fma2(acc[2], a23.x, bb);
        fma2(acc[3], a23.y, bb);
    }
    __syncthreads();
#pragma unroll
    for (int p = 0; p < 4; p++) {
        float2 v = unpk(acc[p]);
        int m = tr * 8 + 2 * p;
        d_hw2part[(size_t)(part * Bq + m) * Wq + n0 + tc] = v.x;
        d_hw2part[(size_t)(part * Bq + m + 1) * Wq + n0 + tc] = v.y;
    }
}

// ---------------- LSTM cell phase ----------------
template <int NPARTS>
__device__ void cell_dev(const float* __restrict__ Xpre, int t, bool is_enc) {
    int idx = blockIdx.x * 256 + threadIdx.x;
    int b = idx >> 9, m = idx & 511;
    const float* xp = Xpre + ((size_t)b * Sq + t) * G4;
    float gi = xp[m], gf = xp[m + 512], gg = xp[m + 1024], go = xp[m + 1536];
#pragma unroll
    for (int ks = 0; ks < NPARTS; ks++) {
        const float* gp = d_gpart + (size_t)(ks * Bq + b) * G4;
        gi += __ldcg(gp + m);
        gf += __ldcg(gp + m + 512);
        gg += __ldcg(gp + m + 1024);
        go += __ldcg(gp + m + 1536);
    }
    float cv = d_c[idx];
    float cn = fsigmoid(gf) * cv + fsigmoid(gi) * ftanh_acc(gg);
    float hn = fsigmoid(go) * ftanh_acc(cn);
    d_h[idx] = hn;
    if (is_enc) {
        d_c[idx] = cn;
        d_enc_out[((size_t)b * Sq + t) * Hq + m] = hn;
    }
}

// ---------------- log-softmax row b, decode step t (256 thr) ----------------
__device__ void softmax_dev(int b, int t, float* __restrict__ out, float* red) {
    const int tid = threadIdx.x;
    float v = __ldcg(&d_sc[b * Sq + tid]);
    red[tid] = v;
    __syncthreads();
    for (int st = 128; st; st >>= 1) {
        if (tid < st) red[tid] = fmaxf(red[tid], red[tid + st]);
        __syncthreads();
    }
    float mx = red[0];
    __syncthreads();
    red[tid] = __expf(v - mx);
    __syncthreads();
    for (int st = 128; st; st >>= 1) {
        if (tid < st) red[tid] += red[tid + st];
        __syncthreads();
    }
    float lse = mx + __logf(red[0]);
    out[((size_t)b * Sq + t) * Sq + tid] = v - lse;
    __syncthreads();
}

// ---------------- persistent encoder (+ e1 tail) ----------------
__global__ void __launch_bounds__(256, 1) enc_persist_k(const float* __restrict__ Xenc) {
    __shared__ __align__(16) float pool[8448];
    float* sA = pool;
    float* sB = pool + 4352;
    unsigned ph = 0;
    const int blk = blockIdx.x;
    const int n0 = (blk >> 4) * 256, k0 = (blk & 15) * 32, part = blk & 15;
    for (int t = 0; t < Sq; t++) {
        gemm_G3_unit(d_WhhT_enc, n0, k0, part, sA, sB);
        gbar_ctr(g_ctr_enc, (++ph) * NBLK);
        cell_dev<16>(Xenc, t, true);
        gbar_ctr(g_ctr_enc, (++ph) * NBLK);
    }
    // e1 = enc_out @ w1T: 512 tiles (128 m x 4 n), 4 per block
#pragma unroll
    for (int i = 0; i < 4; i++) {
        int tile = blk * 4 + i;
        int bm = (tile >> 2) * 128, bn = (tile & 3) * 128;
        gemm128_tile_f2(d_enc_out, d_w1T, d_e1, Wq, Hq, bm, bn, pool, pool + 2176);
    }
}

// ---------------- persistent decoder: warp-specialized P3 ----------------
__global__ void __launch_bounds__(256, 1) dec_persist_k(const float* __restrict__ Xdec,
                                                        const float* __restrict__ vt,
                                                        float* __restrict__ out) {
    __shared__ __align__(16) float pool[6976];
    float* sA = pool;              // G: [64][68] = 4352
    float* sB = pool + 4352;       // G: [16][132] = 2112 (W: [64][36] = 2304 fits too)
    float* hw2_s = pool + 6464;    // 512 floats (disjoint from G region)
    unsigned ph = 0;
    const int blk = blockIdx.x;
    const int tid = threadIdx.x;
    const int lane = tid & 31;
    const int b_att = blk >> 1, half = blk & 1;

    float4 vt4[4];
#pragma unroll
    for (int c = 0; c < 4; c++)
        vt4[c] = *reinterpret_cast<const float4*>(vt + (c * 32 + lane) * 4);

    // prologue: G(0) from hT — warps 0..3 of every block
    if (tid < 128) gemm_G4w_unit(d_WhhT_dec, blk, sA, sB);
    gbar_ctr(g_ctr_dec, (++ph) * NBLK);

    for (int t = 0; t < Sq; t++) {
        // P1: cell(t) everywhere; blocks 64..127 also log-softmax(t-1)
        cell_dev<8>(Xdec, t, false);
        if (blk >= 64 && t > 0) softmax_dev(blk - 64, t - 1, out, pool);
        gbar_ctr(g_ctr_dec, (++ph) * NBLK);

        // P2: hw2 partials on ALL 128 blocks (256 threads)
        gemm_W3_unit(d_w2T, blk, sA, sB);
        gbar_ctr(g_ctr_dec, (++ph) * NBLK);

        // P3 (warp-specialized): warps 0-3 G(t+1) on FMA pipe;
        //                        warps 4-7 attention(t) for (b_att, half) on MUFU pipe
        if (tid < 128) {
            if (t < Sq - 1) gemm_G4w_unit(d_WhhT_dec, blk, sA, sB);
        } else {
            att_4w(b_att, half, vt4, hw2_s);
        }
        gbar_ctr(g_ctr_dec, (++ph) * NBLK);
    }

    // epilogue: softmax(255)
    if (blk >= 64) softmax_dev(blk - 64, Sq - 1, out, pool);
}

// ---------------- launch ----------------
extern "C" void kernel_launch(void* const* d_in, const int* in_sizes, int n_in,
                              void* d_out, int out_size) {
    const float* x = (const float*)d_in[0];
    const float* enc_Wih = (const float*)d_in[1];
    const float* enc_Whh = (const float*)d_in[2];
    const float* enc_bih = (const float*)d_in[3];
    const float* enc_bhh = (const float*)d_in[4];
    const float* dec_Wih = (const float*)d_in[5];
    const float* dec_Whh = (const float*)d_in[6];
    const float* dec_bih = (const float*)d_in[7];
    const float* dec_bhh = (const float*)d_in[8];
    const float* w1 = (const float*)d_in[9];
    const float* w2 = (const float*)d_in[10];
    const float* vt = (const float*)d_in[11];
    float* out = (float*)d_out;

    float *WihT_enc, *WihT_dec, *Xenc, *Xdec, *bias_e, *bias_d;
    cudaGetSymbolAddress((void**)&WihT_enc, d_WihT_enc);
    cudaGetSymbolAddress((void**)&WihT_dec, d_WihT_dec);
    cudaGetSymbolAddress((void**)&Xenc, d_Xenc);
    cudaGetSymbolAddress((void**)&Xdec, d_Xdec);
    cudaGetSymbolAddress((void**)&bias_e, d_bias_enc);
    cudaGetSymbolAddress((void**)&bias_d, d_bias_dec);

    // #0
    transpose_all_k<<<3584, dim3(32, 8)>>>(enc_Wih, dec_Wih, enc_Whh, dec_Whh, w1, w2);
    // #1
    prep_small_k<<<128, 256>>>(enc_bih, enc_bhh, dec_bih, dec_bhh);
    // #2, #3: input projections
    gemm128_k<<<dim3(G4 / 128, (Bq * Sq) / 128), 256>>>(x, WihT_enc, bias_e, Xenc, G4, Sq);
    gemm128_k<<<dim3(G4 / 128, (Bq * Sq) / 128), 256>>>(x, WihT_dec, bias_d, Xdec, G4, Sq);
    // #4: encoder (+e1 tail)
    enc_persist_k<<<NBLK, 256>>>(Xenc);
    // #5: decoder
    dec_persist_k<<<NBLK, 256>>>(Xdec, vt, out);
}

// round 15
// speedup vs baseline: 1.0328x; 1.0328x over previous
#include <cuda_runtime.h>
#include <math.h>

#define Bq 64
#define Sq 256
#define Hq 512
#define G4 2048
#define Wq 512
#define NBLK 128u

// ---------------- scratch ----------------
__device__ float d_WihT_enc[Sq * G4];
__device__ float d_WihT_dec[Sq * G4];
__device__ float d_WhhT_enc[Hq * G4];
__device__ float d_WhhT_dec[Hq * G4];
__device__ float d_w1T[Hq * Wq];
__device__ float d_w2T[Hq * Wq];
__device__ float d_bias_enc[G4];
__device__ float d_bias_dec[G4];
__device__ float d_Xenc[(size_t)Bq * Sq * G4];
__device__ float d_Xdec[(size_t)Bq * Sq * G4];
__device__ float d_h[Bq * Hq];
__device__ float d_c[Bq * Hq];
__device__ float d_enc_out[(size_t)Bq * Sq * Hq]; // [B,S,H]
__device__ float d_e1[(size_t)Bq * Sq * Wq];      // [B,S,W]
__device__ float d_gpart[16 * (size_t)Bq * G4];
__device__ float d_hw2part[8 * Bq * Wq];
__device__ float d_sc[Bq * Sq];

// ---------------- monotonic-counter grid barrier ----------------
__device__ __align__(128) unsigned g_ctr_enc[32];
__device__ __align__(128) unsigned g_ctr_dec[32];

__device__ __forceinline__ void gbar_ctr(unsigned* ctr, unsigned target) {
    __syncthreads();
    if (threadIdx.x == 0) {
        unsigned old, one = 1u;
        asm volatile("atom.release.gpu.add.u32 %0, [%1], %2;"
                     : "=r"(old) : "l"(ctr), "r"(one) : "memory");
        unsigned v;
        do {
            asm volatile("ld.acquire.gpu.u32 %0, [%1];" : "=r"(v) : "l"(ctr) : "memory");
        } while (v < target);
    }
    __syncthreads();
}

// ---------------- packed fp32x2 helpers ----------------
__device__ __forceinline__ unsigned long long pack2(float x) {
    unsigned long long r;
    unsigned u = __float_as_uint(x);
    asm("mov.b64 %0, {%1, %1};" : "=l"(r) : "r"(u));
    return r;
}
__device__ __forceinline__ void fma2(unsigned long long& d, unsigned long long a,
                                     unsigned long long b) {
    asm("fma.rn.f32x2 %0, %1, %2, %0;" : "+l"(d) : "l"(a), "l"(b));
}
__device__ __forceinline__ float2 unpk(unsigned long long v) {
    float2 f;
    asm("mov.b64 {%0, %1}, %2;" : "=f"(f.x), "=f"(f.y) : "l"(v));
    return f;
}

// ---------------- math ----------------
__device__ __forceinline__ float ftanh_acc(float x) {
    float ax = fabsf(x);
    float e = __expf(-2.f * ax);
    float r = __fdividef(1.f - e, 1.f + e);
    return copysignf(r, x);
}
__device__ __forceinline__ float fsigmoid(float x) {
    return __fdividef(1.f, 1.f + __expf(-x));
}
__device__ __forceinline__ float htanh(float x) {
    float y;
    asm("tanh.approx.f32 %0, %1;" : "=f"(y) : "f"(x));
    return y;
}

// ---------------- setup: all 6 transposes in ONE kernel ----------------
__global__ void transpose_all_k(const float* __restrict__ eWih, const float* __restrict__ dWih,
                                const float* __restrict__ eWhh, const float* __restrict__ dWhh,
                                const float* __restrict__ w1, const float* __restrict__ w2) {
    __shared__ float tile[32][33];
    int tb = blockIdx.x;
    const float* A;
    float* At;
    int R, C, lt;
    if (tb < 512)       { A = eWih; At = d_WihT_enc; R = G4; C = Sq; lt = tb; }
    else if (tb < 1024) { A = dWih; At = d_WihT_dec; R = G4; C = Sq; lt = tb - 512; }
    else if (tb < 2048) { A = eWhh; At = d_WhhT_enc; R = G4; C = Hq; lt = tb - 1024; }
    else if (tb < 3072) { A = dWhh; At = d_WhhT_dec; R = G4; C = Hq; lt = tb - 2048; }
    else if (tb < 3328) { A = w1;   At = d_w1T;      R = Wq; C = Hq; lt = tb - 3072; }
    else                { A = w2;   At = d_w2T;      R = Wq; C = Hq; lt = tb - 3328; }
    int ntx = C >> 5;
    int c0 = (lt % ntx) << 5, r0 = (lt / ntx) << 5;
    int tx = threadIdx.x, ty = threadIdx.y;
#pragma unroll
    for (int i = 0; i < 32; i += 8)
        tile[ty + i][tx] = A[(size_t)(r0 + ty + i) * C + c0 + tx];
    __syncthreads();
#pragma unroll
    for (int i = 0; i < 32; i += 8)
        At[(size_t)(c0 + ty + i) * R + r0 + tx] = tile[tx][ty + i];
}

__global__ void prep_small_k(const float* __restrict__ ebih, const float* __restrict__ ebhh,
                             const float* __restrict__ dbih, const float* __restrict__ dbhh) {
    int i = blockIdx.x * 256 + threadIdx.x;
    if (i < G4) {
        d_bias_enc[i] = ebih[i] + ebhh[i];
        d_bias_dec[i] = dbih[i] + dbhh[i];
    }
    if (i < Bq * Hq) {
        d_h[i] = 0.f;
        d_c[i] = 0.f;
    }
    if (i < 32) {
        g_ctr_enc[i] = 0u;
        g_ctr_dec[i] = 0u;
    }
}

// ---------------- big GEMM (f32x2): BM=BN=128, BK=16 ----------------
__global__ __launch_bounds__(256) void gemm128_k(const float* __restrict__ A,
                                                 const float* __restrict__ Bm,
                                                 const float* __restrict__ bias,
                                                 float* __restrict__ C, int N, int K) {
    __shared__ float sA[16][136];
    __shared__ float sB[16][136];
    const int bm = blockIdx.y * 128, bn = blockIdx.x * 128;
    const int tid = threadIdx.x;
    const int tx = tid & 15, ty = tid >> 4;
    unsigned long long acc[8][4] = {};
    for (int k0 = 0; k0 < K; k0 += 16) {
#pragma unroll
        for (int q = 0; q < 2; q++) {
            int f = tid * 2 + q;
            int r = f >> 2, c4 = (f & 3) * 4;
            float4 v = *reinterpret_cast<const float4*>(A + (size_t)(bm + r) * K + k0 + c4);
            sA[c4 + 0][r] = v.x;
            sA[c4 + 1][r] = v.y;
            sA[c4 + 2][r] = v.z;
            sA[c4 + 3][r] = v.w;
        }
#pragma unroll
        for (int q = 0; q < 2; q++) {
            int f = tid * 2 + q;
            int r = f >> 5, c = (f & 31) * 4;
            *reinterpret_cast<float4*>(&sB[r][c]) =
                *reinterpret_cast<const float4*>(Bm + (size_t)(k0 + r) * N + bn + c);
        }
        __syncthreads();
#pragma unroll
        for (int kk = 0; kk < 16; kk++) {
            float4 a0 = *reinterpret_cast<float4*>(&sA[kk][ty * 8]);
            float4 a1 = *reinterpret_cast<float4*>(&sA[kk][ty * 8 + 4]);
            ulonglong2 b0 = *reinterpret_cast<ulonglong2*>(&sB[kk][tx * 8]);
            ulonglong2 b1 = *reinterpret_cast<ulonglong2*>(&sB[kk][tx * 8 + 4]);
            unsigned long long bb[4] = {b0.x, b0.y, b1.x, b1.y};
            unsigned long long aa[8] = {pack2(a0.x), pack2(a0.y), pack2(a0.z), pack2(a0.w),
                                        pack2(a1.x), pack2(a1.y), pack2(a1.z), pack2(a1.w)};
#pragma unroll
            for (int i = 0; i < 8; i++)
#pragma unroll
                for (int j = 0; j < 4; j++) fma2(acc[i][j], aa[i], bb[j]);
        }
        __syncthreads();
    }
#pragma unroll
    for (int i = 0; i < 8; i++) {
        int m = bm + ty * 8 + i;
#pragma unroll
        for (int j = 0; j < 4; j++) {
            int n = bn + tx * 8 + j * 2;
            float2 p = unpk(acc[i][j]);
            if (bias) {
                p.x += bias[n];
                p.y += bias[n + 1];
            }
            *reinterpret_cast<float2*>(&C[(size_t)m * N + n]) = p;
        }
    }
}

// ---------------- device e1 tile (f32x2): 128x128, K=512; A via ldcg ----------------
__device__ void gemm128_tile_f2(const float* __restrict__ A, const float* __restrict__ Bm,
                                float* __restrict__ C, int N, int K, int bm, int bn,
                                float* sAf, float* sBf) {
    const int tid = threadIdx.x;
    const int tx = tid & 15, ty = tid >> 4;
    unsigned long long acc[8][4] = {};
    for (int k0 = 0; k0 < K; k0 += 16) {
#pragma unroll
        for (int q = 0; q < 2; q++) {
            int f = tid * 2 + q;
            int r = f >> 2, c4 = (f & 3) * 4;
            float4 v = __ldcg(reinterpret_cast<const float4*>(A + (size_t)(bm + r) * K + k0 + c4));
            sAf[(c4 + 0) * 136 + r] = v.x;
            sAf[(c4 + 1) * 136 + r] = v.y;
            sAf[(c4 + 2) * 136 + r] = v.z;
            sAf[(c4 + 3) * 136 + r] = v.w;
        }
#pragma unroll
        for (int q = 0; q < 2; q++) {
            int f = tid * 2 + q;
            int r = f >> 5, c = (f & 31) * 4;
            *reinterpret_cast<float4*>(&sBf[r * 136 + c]) =
                *reinterpret_cast<const float4*>(Bm + (size_t)(k0 + r) * N + bn + c);
        }
        __syncthreads();
#pragma unroll
        for (int kk = 0; kk < 16; kk++) {
            float4 a0 = *reinterpret_cast<float4*>(&sAf[kk * 136 + ty * 8]);
            float4 a1 = *reinterpret_cast<float4*>(&sAf[kk * 136 + ty * 8 + 4]);
            ulonglong2 b0 = *reinterpret_cast<ulonglong2*>(&sBf[kk * 136 + tx * 8]);
            ulonglong2 b1 = *reinterpret_cast<ulonglong2*>(&sBf[kk * 136 + tx * 8 + 4]);
            unsigned long long bb[4] = {b0.x, b0.y, b1.x, b1.y};
            unsigned long long aa[8] = {pack2(a0.x), pack2(a0.y), pack2(a0.z), pack2(a0.w),
                                        pack2(a1.x), pack2(a1.y), pack2(a1.z), pack2(a1.w)};
#pragma unroll
            for (int i = 0; i < 8; i++)
#pragma unroll
                for (int j = 0; j < 4; j++) fma2(acc[i][j], aa[i], bb[j]);
        }
        __syncthreads();
    }
#pragma unroll
    for (int i = 0; i < 8; i++) {
        int m = bm + ty * 8 + i;
#pragma unroll
        for (int j = 0; j < 4; j++) {
            float2 p = unpk(acc[i][j]);
            *reinterpret_cast<float2*>(&C[(size_t)m * N + bn + tx * 8 + j * 2]) = p;
        }
    }
}

// ---------------- G unit (f32x2, 256 thr): out 64m x 256n, K=32 slice ----------------
// 128 units: n0=(u>>4)*256, k0=(u&15)*32, part=u&15. sA [32][68]; sB [16][256].
__device__ __forceinline__ void gemm_G3_unit(const float* __restrict__ Bm, int n0, int k0,
                                             int part, float* sA, float* sB) {
    const int tid = threadIdx.x;
#pragma unroll
    for (int i = 0; i < 2; i++) {
        int f = tid + i * 256;
        int m = f >> 3, kq = (f & 7) * 4;
        float4 av = __ldcg(reinterpret_cast<const float4*>(d_h + m * Hq + k0 + kq));
        sA[(kq + 0) * 68 + m] = av.x;
        sA[(kq + 1) * 68 + m] = av.y;
        sA[(kq + 2) * 68 + m] = av.z;
        sA[(kq + 3) * 68 + m] = av.w;
    }
    const int tr = tid >> 5, tc = tid & 31;
    unsigned long long acc[8][4] = {};
    for (int ch = 0; ch < 2; ch++) {
#pragma unroll
        for (int i = 0; i < 4; i++) {
            int f = tid + i * 256;
            int kk = f >> 6, c = (f & 63) * 4;
            *reinterpret_cast<float4*>(&sB[kk * 256 + c]) =
                *reinterpret_cast<const float4*>(Bm + (size_t)(k0 + ch * 16 + kk) * G4 + n0 + c);
        }
        __syncthreads();
#pragma unroll
        for (int kk = 0; kk < 16; kk++) {
            int kg = ch * 16 + kk;
            float4 a0 = *reinterpret_cast<float4*>(&sA[kg * 68 + tr * 8]);
            float4 a1 = *reinterpret_cast<float4*>(&sA[kg * 68 + tr * 8 + 4]);
            ulonglong2 b0 = *reinterpret_cast<ulonglong2*>(&sB[kk * 256 + tc * 4]);
            ulonglong2 b1 = *reinterpret_cast<ulonglong2*>(&sB[kk * 256 + 128 + tc * 4]);
            unsigned long long aa[8] = {pack2(a0.x), pack2(a0.y), pack2(a0.z), pack2(a0.w),
                                        pack2(a1.x), pack2(a1.y), pack2(a1.z), pack2(a1.w)};
#pragma unroll
            for (int i = 0; i < 8; i++) {
                fma2(acc[i][0], aa[i], b0.x);
                fma2(acc[i][1], aa[i], b0.y);
                fma2(acc[i][2], aa[i], b1.x);
                fma2(acc[i][3], aa[i], b1.y);
            }
        }
        __syncthreads();
    }
#pragma unroll
    for (int i = 0; i < 8; i++) {
        int m = tr * 8 + i;
        float* dst = &d_gpart[(size_t)(part * Bq + m) * G4 + n0 + tc * 4];
        ulonglong2 s0;
        s0.x = acc[i][0];
        s0.y = acc[i][1];
        *reinterpret_cast<ulonglong2*>(dst) = s0;
        ulonglong2 s1;
        s1.x = acc[i][2];
        s1.y = acc[i][3];
        *reinterpret_cast<ulonglong2*>(dst + 128) = s1;
    }
}

// ---------------- W unit (f32x2, 256 thr): out 64m x 32n, K=64 slice; 128 units -----
__device__ __forceinline__ void gemm_W3_unit(const float* __restrict__ w2T, int u,
                                             float* sA, float* sB) {
    const int n0 = (u >> 3) * 32, k0 = (u & 7) * 64, part = u & 7;
    const int tid = threadIdx.x;
#pragma unroll
    for (int i = 0; i < 4; i++) {
        int f = tid + i * 256;
        int m = f >> 4, kq = (f & 15) * 4;
        float4 av = __ldcg(reinterpret_cast<const float4*>(d_h + m * Hq + k0 + kq));
        sA[(kq + 0) * 68 + m] = av.x;
        sA[(kq + 1) * 68 + m] = av.y;
        sA[(kq + 2) * 68 + m] = av.z;
        sA[(kq + 3) * 68 + m] = av.w;
    }
#pragma unroll
    for (int q = 0; q < 2; q++) {
        int f = tid * 2 + q;
        int kk = f >> 3, c = (f & 7) * 4;
        *reinterpret_cast<float4*>(&sB[kk * 36 + c]) =
            *reinterpret_cast<const float4*>(w2T + (size_t)(k0 + kk) * Wq + n0 + c);
    }
    __syncthreads();
    const int tr = tid >> 5, tc = tid & 31;
    unsigned long long acc[4] = {};
#pragma unroll
    for (int kk = 0; kk < 64; kk++) {
        ulonglong2 a01 = *reinterpret_cast<ulonglong2*>(&sA[kk * 68 + tr * 8]);
        ulonglong2 a23 = *reinterpret_cast<ulonglong2*>(&sA[kk * 68 + tr * 8 + 4]);
        unsigned long long bb = pack2(sB[kk * 36 + tc]);
        fma2(acc[0], a01.x, bb);
        fma2(acc[1], a01.y, bb);
        fma2(acc[2], a23.x, bb);
        fma2(acc[3], a23.y, bb);
    }
    __syncthreads();
#pragma unroll
    for (int p = 0; p < 4; p++) {
        float2 v = unpk(acc[p]);
        int m = tr * 8 + 2 * p;
        d_hw2part[(size_t)(part * Bq + m) * Wq + n0 + tc] = v.x;
        d_hw2part[(size_t)(part * Bq + m + 1) * Wq + n0 + tc] = v.y;
    }
}

// ---------------- LSTM cell phase ----------------
template <int NPARTS>
__device__ void cell_dev(const float* __restrict__ Xpre, int t, bool is_enc) {
    int idx = blockIdx.x * 256 + threadIdx.x;
    int b = idx >> 9, m = idx & 511;
    const float* xp = Xpre + ((size_t)b * Sq + t) * G4;
    float gi = xp[m], gf = xp[m + 512], gg = xp[m + 1024], go = xp[m + 1536];
#pragma unroll
    for (int ks = 0; ks < NPARTS; ks++) {
        const float* gp = d_gpart + (size_t)(ks * Bq + b) * G4;
        gi += __ldcg(gp + m);
        gf += __ldcg(gp + m + 512);
        gg += __ldcg(gp + m + 1024);
        go += __ldcg(gp + m + 1536);
    }
    float cv = d_c[idx];
    float cn = fsigmoid(gf) * cv + fsigmoid(gi) * ftanh_acc(gg);
    float hn = fsigmoid(go) * ftanh_acc(cn);
    d_h[idx] = hn;
    if (is_enc) {
        d_c[idx] = cn;
        d_enc_out[((size_t)b * Sq + t) * Hq + m] = hn;
    }
}

// ---------------- attention for (b, half): 256 threads, prefetched e1 ----------------
__device__ void att_half(int b, int half, const float4* vt4, float* hw2_s) {
    const int tid = threadIdx.x, lane = tid & 31, wid = tid >> 5;
#pragma unroll
    for (int r = 0; r < 2; r++) {
        int w = tid + r * 256;
        float s = 0.f;
#pragma unroll
        for (int p = 0; p < 8; p++)
            s += __ldcg(&d_hw2part[(size_t)(p * Bq + b) * Wq + w]);
        hw2_s[w] = s;
    }
    __syncthreads();
    float4 hv[4];
#pragma unroll
    for (int c = 0; c < 4; c++)
        hv[c] = *reinterpret_cast<float4*>(&hw2_s[(c * 32 + lane) * 4]);

    const int s0 = half * 128;
    float4 ev[4];
    {
        const float* ep = d_e1 + ((size_t)b * Sq + s0 + wid) * Wq;
#pragma unroll
        for (int c = 0; c < 4; c++)
            ev[c] = __ldg(reinterpret_cast<const float4*>(ep + (c * 32 + lane) * 4));
    }
    for (int s = s0 + wid; s < s0 + 128; s += 8) {
        float4 evn[4];
        if (s + 8 < s0 + 128) {
            const float* epn = d_e1 + ((size_t)b * Sq + s + 8) * Wq;
#pragma unroll
            for (int c = 0; c < 4; c++)
                evn[c] = __ldg(reinterpret_cast<const float4*>(epn + (c * 32 + lane) * 4));
        }
        float sum = 0.f;
#pragma unroll
        for (int c = 0; c < 4; c++) {
            sum += vt4[c].x * htanh(ev[c].x + hv[c].x);
            sum += vt4[c].y * htanh(ev[c].y + hv[c].y);
            sum += vt4[c].z * htanh(ev[c].z + hv[c].z);
            sum += vt4[c].w * htanh(ev[c].w + hv[c].w);
        }
#pragma unroll
        for (int off = 16; off; off >>= 1) sum += __shfl_xor_sync(0xffffffffu, sum, off);
        if (lane == 0) d_sc[b * Sq + s] = sum;
#pragma unroll
        for (int c = 0; c < 4; c++) ev[c] = evn[c];
    }
    __syncthreads();
}

// ---------------- log-softmax row b, decode step t (256 thr) ----------------
__device__ void softmax_dev(int b, int t, float* __restrict__ out, float* red) {
    const int tid = threadIdx.x;
    float v = __ldcg(&d_sc[b * Sq + tid]);
    red[tid] = v;
    __syncthreads();
    for (int st = 128; st; st >>= 1) {
        if (tid < st) red[tid] = fmaxf(red[tid], red[tid + st]);
        __syncthreads();
    }
    float mx = red[0];
    __syncthreads();
    red[tid] = __expf(v - mx);
    __syncthreads();
    for (int st = 128; st; st >>= 1) {
        if (tid < st) red[tid] += red[tid + st];
        __syncthreads();
    }
    float lse = mx + __logf(red[0]);
    out[((size_t)b * Sq + t) * Sq + tid] = v - lse;
    __syncthreads();
}

// ---------------- persistent encoder (+ e1 tail) ----------------
__global__ void __launch_bounds__(256, 1) enc_persist_k(const float* __restrict__ Xenc) {
    __shared__ __align__(16) float pool[8448];
    float* sA = pool;
    float* sB = pool + 4352;
    unsigned ph = 0;
    const int blk = blockIdx.x;
    const int n0 = (blk >> 4) * 256, k0 = (blk & 15) * 32, part = blk & 15;
    for (int t = 0; t < Sq; t++) {
        gemm_G3_unit(d_WhhT_enc, n0, k0, part, sA, sB);
        gbar_ctr(g_ctr_enc, (++ph) * NBLK);
        cell_dev<16>(Xenc, t, true);
        gbar_ctr(g_ctr_enc, (++ph) * NBLK);
    }
    // e1 = enc_out @ w1T: 512 tiles (128 m x 4 n), 4 per block
#pragma unroll
    for (int i = 0; i < 4; i++) {
        int tile = blk * 4 + i;
        int bm = (tile >> 2) * 128, bn = (tile & 3) * 128;
        gemm128_tile_f2(d_enc_out, d_w1T, d_e1, Wq, Hq, bm, bn, pool, pool + 2176);
    }
}

// ---------------- persistent decoder: full-grid att phase ----------------
__global__ void __launch_bounds__(256, 1) dec_persist_k(const float* __restrict__ Xdec,
                                                        const float* __restrict__ vt,
                                                        float* __restrict__ out) {
    __shared__ __align__(16) float pool[8448];
    float* sA = pool;
    float* sB = pool + 4352;
    unsigned ph = 0;
    const int blk = blockIdx.x;
    const int lane = threadIdx.x & 31;
    const int n0 = (blk >> 4) * 256, k0 = (blk & 15) * 32, part = blk & 15;
    const int b_att = blk >> 1, half = blk & 1;

    float4 vt4[4];
#pragma unroll
    for (int c = 0; c < 4; c++)
        vt4[c] = *reinterpret_cast<const float4*>(vt + (c * 32 + lane) * 4);

    // prologue: G(0) from hT — all 128 blocks
    gemm_G3_unit(d_WhhT_dec, n0, k0, part, sA, sB);
    gbar_ctr(g_ctr_dec, (++ph) * NBLK);

    for (int t = 0; t < Sq; t++) {
        // P1: cell(t) everywhere; blocks 64..127 also log-softmax(t-1)
        cell_dev<16>(Xdec, t, false);
        if (blk >= 64 && t > 0) softmax_dev(blk - 64, t - 1, out, pool);
        gbar_ctr(g_ctr_dec, (++ph) * NBLK);

        // P2: G(t+1) on ALL 128 blocks (FMA roofline) + W micro-unit
        if (t < Sq - 1) gemm_G3_unit(d_WhhT_dec, n0, k0, part, sA, sB);
        gemm_W3_unit(d_w2T, blk, sA, sB);
        gbar_ctr(g_ctr_dec, (++ph) * NBLK);

        // P3: attention(t) for (b, half) on ALL 128 blocks -> e1 stream at chip L2 floor
        att_half(b_att, half, vt4, pool);
        gbar_ctr(g_ctr_dec, (++ph) * NBLK);
    }

    // epilogue: softmax(255)
    if (blk >= 64) softmax_dev(blk - 64, Sq - 1, out, pool);
}

// ---------------- launch ----------------
extern "C" void kernel_launch(void* const* d_in, const int* in_sizes, int n_in,
                              void* d_out, int out_size) {
    const float* x = (const float*)d_in[0];
    const float* enc_Wih = (const float*)d_in[1];
    const float* enc_Whh = (const float*)d_in[2];
    const float* enc_bih = (const float*)d_in[3];
    const float* enc_bhh = (const float*)d_in[4];
    const float* dec_Wih = (const float*)d_in[5];
    const float* dec_Whh = (const float*)d_in[6];
    const float* dec_bih = (const float*)d_in[7];
    const float* dec_bhh = (const float*)d_in[8];
    const float* w1 = (const float*)d_in[9];
    const float* w2 = (const float*)d_in[10];
    const float* vt = (const float*)d_in[11];
    float* out = (float*)d_out;

    float *WihT_enc, *WihT_dec, *Xenc, *Xdec, *bias_e, *bias_d;
    cudaGetSymbolAddress((void**)&WihT_enc, d_WihT_enc);
    cudaGetSymbolAddress((void**)&WihT_dec, d_WihT_dec);
    cudaGetSymbolAddress((void**)&Xenc, d_Xenc);
    cudaGetSymbolAddress((void**)&Xdec, d_Xdec);
    cudaGetSymbolAddress((void**)&bias_e, d_bias_enc);
    cudaGetSymbolAddress((void**)&bias_d, d_bias_dec);

    // #0
    transpose_all_k<<<3584, dim3(32, 8)>>>(enc_Wih, dec_Wih, enc_Whh, dec_Whh, w1, w2);
    // #1
    prep_small_k<<<128, 256>>>(enc_bih, enc_bhh, dec_bih, dec_bhh);
    // #2, #3: input projections
    gemm128_k<<<dim3(G4 / 128, (Bq * Sq) / 128), 256>>>(x, WihT_enc, bias_e, Xenc, G4, Sq);
    gemm128_k<<<dim3(G4 / 128, (Bq * Sq) / 128), 256>>>(x, WihT_dec, bias_d, Xdec, G4, Sq);
    // #4: encoder (+e1 tail)
    enc_persist_k<<<NBLK, 256>>>(Xenc);
    // #5: decoder
    dec_persist_k<<<NBLK, 256>>>(Xdec, vt, out);
}

// round 16
// speedup vs baseline: 1.2655x; 1.2252x over previous
#include <cuda_runtime.h>
#include <math.h>

#define Bq 64
#define Sq 256
#define Hq 512
#define G4 2048
#define Wq 512
#define NBLK 128u

// ---------------- scratch ----------------
__device__ float d_WihT_enc[Sq * G4];
__device__ float d_WihT_dec[Sq * G4];
__device__ float d_WhhT_enc[Hq * G4];
__device__ float d_WhhT_dec[Hq * G4];
__device__ float d_w1T[Hq * Wq];
__device__ float d_w2T[Hq * Wq];
__device__ float d_bias_enc[G4];
__device__ float d_bias_dec[G4];
__device__ float d_Xenc[(size_t)Bq * Sq * G4];
__device__ float d_Xdec[(size_t)Bq * Sq * G4];
__device__ float d_h[Bq * Hq];
__device__ float d_c[Bq * Hq];
__device__ float d_enc_out[(size_t)Bq * Sq * Hq];  // [B,S,H] rows b*Sq+s
__device__ float d_e1[(size_t)Bq * Sq * Wq];       // [B,S,W] rows b*Sq+s
__device__ float d_hdec[(size_t)Sq * Bq * Hq];     // [T,B,H] rows t*Bq+b
__device__ float d_hw2all[(size_t)Sq * Bq * Wq];   // [T,B,W] rows t*Bq+b
__device__ float d_gpart[16 * (size_t)Bq * G4];

// ---------------- monotonic-counter grid barrier ----------------
__device__ __align__(128) unsigned g_ctr_enc[32];
__device__ __align__(128) unsigned g_ctr_dec[32];

__device__ __forceinline__ void gbar_ctr(unsigned* ctr, unsigned target) {
    __syncthreads();
    if (threadIdx.x == 0) {
        unsigned old, one = 1u;
        asm volatile("atom.release.gpu.add.u32 %0, [%1], %2;"
                     : "=r"(old) : "l"(ctr), "r"(one) : "memory");
        unsigned v;
        do {
            asm volatile("ld.acquire.gpu.u32 %0, [%1];" : "=r"(v) : "l"(ctr) : "memory");
        } while (v < target);
    }
    __syncthreads();
}

// ---------------- packed fp32x2 helpers ----------------
__device__ __forceinline__ unsigned long long pack2(float x) {
    unsigned long long r;
    unsigned u = __float_as_uint(x);
    asm("mov.b64 %0, {%1, %1};" : "=l"(r) : "r"(u));
    return r;
}
__device__ __forceinline__ void fma2(unsigned long long& d, unsigned long long a,
                                     unsigned long long b) {
    asm("fma.rn.f32x2 %0, %1, %2, %0;" : "+l"(d) : "l"(a), "l"(b));
}
__device__ __forceinline__ float2 unpk(unsigned long long v) {
    float2 f;
    asm("mov.b64 {%0, %1}, %2;" : "=f"(f.x), "=f"(f.y) : "l"(v));
    return f;
}

// ---------------- math ----------------
__device__ __forceinline__ float ftanh_acc(float x) {
    float ax = fabsf(x);
    float e = __expf(-2.f * ax);
    float r = __fdividef(1.f - e, 1.f + e);
    return copysignf(r, x);
}
__device__ __forceinline__ float fsigmoid(float x) {
    return __fdividef(1.f, 1.f + __expf(-x));
}
__device__ __forceinline__ float htanh(float x) {
    float y;
    asm("tanh.approx.f32 %0, %1;" : "=f"(y) : "f"(x));
    return y;
}

// ---------------- setup: all 6 transposes in ONE kernel ----------------
__global__ void transpose_all_k(const float* __restrict__ eWih, const float* __restrict__ dWih,
                                const float* __restrict__ eWhh, const float* __restrict__ dWhh,
                                const float* __restrict__ w1, const float* __restrict__ w2) {
    __shared__ float tile[32][33];
    int tb = blockIdx.x;
    const float* A;
    float* At;
    int R, C, lt;
    if (tb < 512)       { A = eWih; At = d_WihT_enc; R = G4; C = Sq; lt = tb; }
    else if (tb < 1024) { A = dWih; At = d_WihT_dec; R = G4; C = Sq; lt = tb - 512; }
    else if (tb < 2048) { A = eWhh; At = d_WhhT_enc; R = G4; C = Hq; lt = tb - 1024; }
    else if (tb < 3072) { A = dWhh; At = d_WhhT_dec; R = G4; C = Hq; lt = tb - 2048; }
    else if (tb < 3328) { A = w1;   At = d_w1T;      R = Wq; C = Hq; lt = tb - 3072; }
    else                { A = w2;   At = d_w2T;      R = Wq; C = Hq; lt = tb - 3328; }
    int ntx = C >> 5;
    int c0 = (lt % ntx) << 5, r0 = (lt / ntx) << 5;
    int tx = threadIdx.x, ty = threadIdx.y;
#pragma unroll
    for (int i = 0; i < 32; i += 8)
        tile[ty + i][tx] = A[(size_t)(r0 + ty + i) * C + c0 + tx];
    __syncthreads();
#pragma unroll
    for (int i = 0; i < 32; i += 8)
        At[(size_t)(c0 + ty + i) * R + r0 + tx] = tile[tx][ty + i];
}

__global__ void prep_small_k(const float* __restrict__ ebih, const float* __restrict__ ebhh,
                             const float* __restrict__ dbih, const float* __restrict__ dbhh) {
    int i = blockIdx.x * 256 + threadIdx.x;
    if (i < G4) {
        d_bias_enc[i] = ebih[i] + ebhh[i];
        d_bias_dec[i] = dbih[i] + dbhh[i];
    }
    if (i < Bq * Hq) {
        d_h[i] = 0.f;
        d_c[i] = 0.f;
    }
    if (i < 32) {
        g_ctr_enc[i] = 0u;
        g_ctr_dec[i] = 0u;
    }
}

// ---------------- big GEMM (f32x2): BM=BN=128, BK=16 ----------------
__global__ __launch_bounds__(256) void gemm128_k(const float* __restrict__ A,
                                                 const float* __restrict__ Bm,
                                                 const float* __restrict__ bias,
                                                 float* __restrict__ C, int N, int K) {
    __shared__ float sA[16][136];
    __shared__ float sB[16][136];
    const int bm = blockIdx.y * 128, bn = blockIdx.x * 128;
    const int tid = threadIdx.x;
    const int tx = tid & 15, ty = tid >> 4;
    unsigned long long acc[8][4] = {};
    for (int k0 = 0; k0 < K; k0 += 16) {
#pragma unroll
        for (int q = 0; q < 2; q++) {
            int f = tid * 2 + q;
            int r = f >> 2, c4 = (f & 3) * 4;
            float4 v = *reinterpret_cast<const float4*>(A + (size_t)(bm + r) * K + k0 + c4);
            sA[c4 + 0][r] = v.x;
            sA[c4 + 1][r] = v.y;
            sA[c4 + 2][r] = v.z;
            sA[c4 + 3][r] = v.w;
        }
#pragma unroll
        for (int q = 0; q < 2; q++) {
            int f = tid * 2 + q;
            int r = f >> 5, c = (f & 31) * 4;
            *reinterpret_cast<float4*>(&sB[r][c]) =
                *reinterpret_cast<const float4*>(Bm + (size_t)(k0 + r) * N + bn + c);
        }
        __syncthreads();
#pragma unroll
        for (int kk = 0; kk < 16; kk++) {
            float4 a0 = *reinterpret_cast<float4*>(&sA[kk][ty * 8]);
            float4 a1 = *reinterpret_cast<float4*>(&sA[kk][ty * 8 + 4]);
            ulonglong2 b0 = *reinterpret_cast<ulonglong2*>(&sB[kk][tx * 8]);
            ulonglong2 b1 = *reinterpret_cast<ulonglong2*>(&sB[kk][tx * 8 + 4]);
            unsigned long long bb[4] = {b0.x, b0.y, b1.x, b1.y};
            unsigned long long aa[8] = {pack2(a0.x), pack2(a0.y), pack2(a0.z), pack2(a0.w),
                                        pack2(a1.x), pack2(a1.y), pack2(a1.z), pack2(a1.w)};
#pragma unroll
            for (int i = 0; i < 8; i++)
#pragma unroll
                for (int j = 0; j < 4; j++) fma2(acc[i][j], aa[i], bb[j]);
        }
        __syncthreads();
    }
#pragma unroll
    for (int i = 0; i < 8; i++) {
        int m = bm + ty * 8 + i;
#pragma unroll
        for (int j = 0; j < 4; j++) {
            int n = bn + tx * 8 + j * 2;
            float2 p = unpk(acc[i][j]);
            if (bias) {
                p.x += bias[n];
                p.y += bias[n + 1];
            }
            *reinterpret_cast<float2*>(&C[(size_t)m * N + n]) = p;
        }
    }
}

// ---------------- device e1 tile (f32x2): 128x128, K=512; A via ldcg ----------------
__device__ void gemm128_tile_f2(const float* __restrict__ A, const float* __restrict__ Bm,
                                float* __restrict__ C, int N, int K, int bm, int bn,
                                float* sAf, float* sBf) {
    const int tid = threadIdx.x;
    const int tx = tid & 15, ty = tid >> 4;
    unsigned long long acc[8][4] = {};
    for (int k0 = 0; k0 < K; k0 += 16) {
#pragma unroll
        for (int q = 0; q < 2; q++) {
            int f = tid * 2 + q;
            int r = f >> 2, c4 = (f & 3) * 4;
            float4 v = __ldcg(reinterpret_cast<const float4*>(A + (size_t)(bm + r) * K + k0 + c4));
            sAf[(c4 + 0) * 136 + r] = v.x;
            sAf[(c4 + 1) * 136 + r] = v.y;
            sAf[(c4 + 2) * 136 + r] = v.z;
            sAf[(c4 + 3) * 136 + r] = v.w;
        }
#pragma unroll
        for (int q = 0; q < 2; q++) {
            int f = tid * 2 + q;
            int r = f >> 5, c = (f & 31) * 4;
            *reinterpret_cast<float4*>(&sBf[r * 136 + c]) =
                *reinterpret_cast<const float4*>(Bm + (size_t)(k0 + r) * N + bn + c);
        }
        __syncthreads();
#pragma unroll
        for (int kk = 0; kk < 16; kk++) {
            float4 a0 = *reinterpret_cast<float4*>(&sAf[kk * 136 + ty * 8]);
            float4 a1 = *reinterpret_cast<float4*>(&sAf[kk * 136 + ty * 8 + 4]);
            ulonglong2 b0 = *reinterpret_cast<ulonglong2*>(&sBf[kk * 136 + tx * 8]);
            ulonglong2 b1 = *reinterpret_cast<ulonglong2*>(&sBf[kk * 136 + tx * 8 + 4]);
            unsigned long long bb[4] = {b0.x, b0.y, b1.x, b1.y};
            unsigned long long aa[8] = {pack2(a0.x), pack2(a0.y), pack2(a0.z), pack2(a0.w),
                                        pack2(a1.x), pack2(a1.y), pack2(a1.z), pack2(a1.w)};
#pragma unroll
            for (int i = 0; i < 8; i++)
#pragma unroll
                for (int j = 0; j < 4; j++) fma2(acc[i][j], aa[i], bb[j]);
        }
        __syncthreads();
    }
#pragma unroll
    for (int i = 0; i < 8; i++) {
        int m = bm + ty * 8 + i;
#pragma unroll
        for (int j = 0; j < 4; j++) {
            float2 p = unpk(acc[i][j]);
            *reinterpret_cast<float2*>(&C[(size_t)m * N + bn + tx * 8 + j * 2]) = p;
        }
    }
}

// ---------------- G unit (f32x2, 256 thr): out 64m x 256n, K=32 slice ----------------
// 128 units: n0=(u>>4)*256, k0=(u&15)*32, part=u&15. sA [32][68]; sB [16][256].
__device__ __forceinline__ void gemm_G3_unit(const float* __restrict__ Bm, int n0, int k0,
                                             int part, float* sA, float* sB) {
    const int tid = threadIdx.x;
#pragma unroll
    for (int i = 0; i < 2; i++) {
        int f = tid + i * 256;
        int m = f >> 3, kq = (f & 7) * 4;
        float4 av = __ldcg(reinterpret_cast<const float4*>(d_h + m * Hq + k0 + kq));
        sA[(kq + 0) * 68 + m] = av.x;
        sA[(kq + 1) * 68 + m] = av.y;
        sA[(kq + 2) * 68 + m] = av.z;
        sA[(kq + 3) * 68 + m] = av.w;
    }
    const int tr = tid >> 5, tc = tid & 31;
    unsigned long long acc[8][4] = {};
    for (int ch = 0; ch < 2; ch++) {
#pragma unroll
        for (int i = 0; i < 4; i++) {
            int f = tid + i * 256;
            int kk = f >> 6, c = (f & 63) * 4;
            *reinterpret_cast<float4*>(&sB[kk * 256 + c]) =
                *reinterpret_cast<const float4*>(Bm + (size_t)(k0 + ch * 16 + kk) * G4 + n0 + c);
        }
        __syncthreads();
#pragma unroll
        for (int kk = 0; kk < 16; kk++) {
            int kg = ch * 16 + kk;
            float4 a0 = *reinterpret_cast<float4*>(&sA[kg * 68 + tr * 8]);
            float4 a1 = *reinterpret_cast<float4*>(&sA[kg * 68 + tr * 8 + 4]);
            ulonglong2 b0 = *reinterpret_cast<ulonglong2*>(&sB[kk * 256 + tc * 4]);
            ulonglong2 b1 = *reinterpret_cast<ulonglong2*>(&sB[kk * 256 + 128 + tc * 4]);
            unsigned long long aa[8] = {pack2(a0.x), pack2(a0.y), pack2(a0.z), pack2(a0.w),
                                        pack2(a1.x), pack2(a1.y), pack2(a1.z), pack2(a1.w)};
#pragma unroll
            for (int i = 0; i < 8; i++) {
                fma2(acc[i][0], aa[i], b0.x);
                fma2(acc[i][1], aa[i], b0.y);
                fma2(acc[i][2], aa[i], b1.x);
                fma2(acc[i][3], aa[i], b1.y);
            }
        }
        __syncthreads();
    }
#pragma unroll
    for (int i = 0; i < 8; i++) {
        int m = tr * 8 + i;
        float* dst = &d_gpart[(size_t)(part * Bq + m) * G4 + n0 + tc * 4];
        ulonglong2 s0;
        s0.x = acc[i][0];
        s0.y = acc[i][1];
        *reinterpret_cast<ulonglong2*>(dst) = s0;
        ulonglong2 s1;
        s1.x = acc[i][2];
        s1.y = acc[i][3];
        *reinterpret_cast<ulonglong2*>(dst + 128) = s1;
    }
}

// ---------------- LSTM cell phase. MODE 0 = encoder, 1 = decoder-recurrence -------
template <int MODE>
__device__ void cell_dev(const float* __restrict__ Xpre, int t) {
    int idx = blockIdx.x * 256 + threadIdx.x;
    int b = idx >> 9, m = idx & 511;
    const float* xp = Xpre + ((size_t)b * Sq + t) * G4;
    float gi = xp[m], gf = xp[m + 512], gg = xp[m + 1024], go = xp[m + 1536];
#pragma unroll
    for (int ks = 0; ks < 16; ks++) {
        const float* gp = d_gpart + (size_t)(ks * Bq + b) * G4;
        gi += __ldcg(gp + m);
        gf += __ldcg(gp + m + 512);
        gg += __ldcg(gp + m + 1024);
        go += __ldcg(gp + m + 1536);
    }
    float cv = d_c[idx];
    float cn = fsigmoid(gf) * cv + fsigmoid(gi) * ftanh_acc(gg);
    float hn = fsigmoid(go) * ftanh_acc(cn);
    d_h[idx] = hn;
    if (MODE == 0) {
        d_c[idx] = cn;
        d_enc_out[((size_t)b * Sq + t) * Hq + m] = hn;   // [B,S,H]
    } else {
        d_hdec[((size_t)t * Bq + b) * Hq + m] = hn;      // [T,B,H]
    }
}

// ---------------- persistent encoder (+ e1 tail) ----------------
__global__ void __launch_bounds__(256, 1) enc_persist_k(const float* __restrict__ Xenc) {
    __shared__ __align__(16) float pool[8448];
    float* sA = pool;
    float* sB = pool + 4352;
    unsigned ph = 0;
    const int blk = blockIdx.x;
    const int n0 = (blk >> 4) * 256, k0 = (blk & 15) * 32, part = blk & 15;
    for (int t = 0; t < Sq; t++) {
        gemm_G3_unit(d_WhhT_enc, n0, k0, part, sA, sB);
        gbar_ctr(g_ctr_enc, (++ph) * NBLK);
        cell_dev<0>(Xenc, t);
        gbar_ctr(g_ctr_enc, (++ph) * NBLK);
    }
    // e1 = enc_out @ w1T: 512 tiles (128 m x 4 n), 4 per block
#pragma unroll
    for (int i = 0; i < 4; i++) {
        int tile = blk * 4 + i;
        int bm = (tile >> 2) * 128, bn = (tile & 3) * 128;
        gemm128_tile_f2(d_enc_out, d_w1T, d_e1, Wq, Hq, bm, bn, pool, pool + 2176);
    }
}

// ---------------- persistent decoder RECURRENCE ONLY ----------------
__global__ void __launch_bounds__(256, 1) dec_rec_persist_k(const float* __restrict__ Xdec) {
    __shared__ __align__(16) float pool[8448];
    float* sA = pool;
    float* sB = pool + 4352;
    unsigned ph = 0;
    const int blk = blockIdx.x;
    const int n0 = (blk >> 4) * 256, k0 = (blk & 15) * 32, part = blk & 15;
    for (int t = 0; t < Sq; t++) {
        gemm_G3_unit(d_WhhT_dec, n0, k0, part, sA, sB);
        gbar_ctr(g_ctr_dec, (++ph) * NBLK);
        cell_dev<1>(Xdec, t);
        gbar_ctr(g_ctr_dec, (++ph) * NBLK);
    }
}

// ---------------- attention + log-softmax mega-kernel ----------------
// 2048 blocks: b = blk>>5, t0 = (blk&31)*8. Warp w handles t = t0 + w.
__global__ void __launch_bounds__(256) att_all_k(const float* __restrict__ vt,
                                                 float* __restrict__ out) {
    __shared__ float sc_s[8 * 256];
    const int blk = blockIdx.x;
    const int b = blk >> 5, t0 = (blk & 31) * 8;
    const int tid = threadIdx.x;
    const int w = tid >> 5, lane = tid & 31;
    const int t = t0 + w;

    float4 vt4[4], hv[4];
    const float* hp = d_hw2all + ((size_t)t * Bq + b) * Wq;
#pragma unroll
    for (int c = 0; c < 4; c++) {
        vt4[c] = *reinterpret_cast<const float4*>(vt + (c * 32 + lane) * 4);
        hv[c] = __ldg(reinterpret_cast<const float4*>(hp + (c * 32 + lane) * 4));
    }

    const float* e1b = d_e1 + (size_t)b * Sq * Wq;
    float4 ev[4];
#pragma unroll
    for (int c = 0; c < 4; c++)
        ev[c] = __ldg(reinterpret_cast<const float4*>(e1b + (c * 32 + lane) * 4));

    for (int s = 0; s < Sq; s++) {
        float4 evn[4];
        if (s + 1 < Sq) {
            const float* epn = e1b + (size_t)(s + 1) * Wq;
#pragma unroll
            for (int c = 0; c < 4; c++)
                evn[c] = __ldg(reinterpret_cast<const float4*>(epn + (c * 32 + lane) * 4));
        }
        float sum = 0.f;
#pragma unroll
        for (int c = 0; c < 4; c++) {
            sum += vt4[c].x * htanh(ev[c].x + hv[c].x);
            sum += vt4[c].y * htanh(ev[c].y + hv[c].y);
            sum += vt4[c].z * htanh(ev[c].z + hv[c].z);
            sum += vt4[c].w * htanh(ev[c].w + hv[c].w);
        }
#pragma unroll
        for (int off = 16; off; off >>= 1) sum += __shfl_xor_sync(0xffffffffu, sum, off);
        if (lane == 0) sc_s[w * 256 + s] = sum;
#pragma unroll
        for (int c = 0; c < 4; c++) ev[c] = evn[c];
    }
    __syncwarp();

    // per-warp log-softmax over its 256 scores
    float v[8];
    float mx = -1e30f;
#pragma unroll
    for (int i = 0; i < 8; i++) {
        v[i] = sc_s[w * 256 + i * 32 + lane];
        mx = fmaxf(mx, v[i]);
    }
#pragma unroll
    for (int off = 16; off; off >>= 1) mx = fmaxf(mx, __shfl_xor_sync(0xffffffffu, mx, off));
    float se = 0.f;
#pragma unroll
    for (int i = 0; i < 8; i++) se += __expf(v[i] - mx);
#pragma unroll
    for (int off = 16; off; off >>= 1) se += __shfl_xor_sync(0xffffffffu, se, off);
    float lse = mx + __logf(se);
    float* op = out + ((size_t)b * Sq + t) * Sq;
#pragma unroll
    for (int i = 0; i < 8; i++) op[i * 32 + lane] = v[i] - lse;
}

// ---------------- launch ----------------
extern "C" void kernel_launch(void* const* d_in, const int* in_sizes, int n_in,
                              void* d_out, int out_size) {
    const float* x = (const float*)d_in[0];
    const float* enc_Wih = (const float*)d_in[1];
    const float* enc_Whh = (const float*)d_in[2];
    const float* enc_bih = (const float*)d_in[3];
    const float* enc_bhh = (const float*)d_in[4];
    const float* dec_Wih = (const float*)d_in[5];
    const float* dec_Whh = (const float*)d_in[6];
    const float* dec_bih = (const float*)d_in[7];
    const float* dec_bhh = (const float*)d_in[8];
    const float* w1 = (const float*)d_in[9];
    const float* w2 = (const float*)d_in[10];
    const float* vt = (const float*)d_in[11];
    float* out = (float*)d_out;

    float *WihT_enc, *WihT_dec, *w2T, *Xenc, *Xdec, *hdec, *hw2all, *bias_e, *bias_d;
    cudaGetSymbolAddress((void**)&WihT_enc, d_WihT_enc);
    cudaGetSymbolAddress((void**)&WihT_dec, d_WihT_dec);
    cudaGetSymbolAddress((void**)&w2T, d_w2T);
    cudaGetSymbolAddress((void**)&Xenc, d_Xenc);
    cudaGetSymbolAddress((void**)&Xdec, d_Xdec);
    cudaGetSymbolAddress((void**)&hdec, d_hdec);
    cudaGetSymbolAddress((void**)&hw2all, d_hw2all);
    cudaGetSymbolAddress((void**)&bias_e, d_bias_enc);
    cudaGetSymbolAddress((void**)&bias_d, d_bias_dec);

    // #0
    transpose_all_k<<<3584, dim3(32, 8)>>>(enc_Wih, dec_Wih, enc_Whh, dec_Whh, w1, w2);
    // #1
    prep_small_k<<<128, 256>>>(enc_bih, enc_bhh, dec_bih, dec_bhh);
    // #2, #3: input projections
    gemm128_k<<<dim3(G4 / 128, (Bq * Sq) / 128), 256>>>(x, WihT_enc, bias_e, Xenc, G4, Sq);
    gemm128_k<<<dim3(G4 / 128, (Bq * Sq) / 128), 256>>>(x, WihT_dec, bias_d, Xdec, G4, Sq);
    // #4: encoder (+e1 tail)
    enc_persist_k<<<NBLK, 256>>>(Xenc);
    // #5: decoder recurrence only
    dec_rec_persist_k<<<NBLK, 256>>>(Xdec);
    // #6: hw2_all = h_dec_all @ w2T  [16384,512]x[512,512]
    gemm128_k<<<dim3(Wq / 128, (Sq * Bq) / 128), 256>>>(hdec, w2T, (const float*)0,
                                                        hw2all, Wq, Hq);
    // #7: attention + log-softmax (no barriers, 2048 independent blocks)
    att_all_k<<<Bq * 32, 256>>>(vt, out);
}